// round 6
// baseline (speedup 1.0000x reference)
#include <cuda_runtime.h>
#include <cstdint>

// Problem constants
#define BN   4
#define CN   128
#define HN   128
#define WN   128
#define COUT 128
#define DGN  8
#define CG   16
#define KK   9
#define HO   128
#define WO   128
#define NS   72         // (dg,k) positions
#define KT   (NS * 2)   // k8 slices (K = 1152)

// Scratch
__device__ __align__(16) float g_xt[BN * DGN * HN * WN * CG];    // x -> (B,DG,H,W,Cg)
__device__ __align__(16) uint32_t g_wa[KT * 8 * 32 * 4];         // A-fragment-ordered tf32 weights

__device__ __forceinline__ uint32_t f2tf32(float v) {
    uint32_t r;
    asm("cvt.rna.tf32.f32 %0, %1;" : "=r"(r) : "f"(v));
    return r;
}
__device__ __forceinline__ uint32_t s2u(const void* p) {
    uint32_t a;
    asm("{ .reg .u64 t; cvta.to.shared.u64 t, %1; cvt.u32.u64 %0, t; }" : "=r"(a) : "l"(p));
    return a;
}
__device__ __forceinline__ void mma_tf32(float* d, const uint32_t* a, const uint32_t* b) {
    asm volatile(
        "mma.sync.aligned.m16n8k8.row.col.f32.tf32.tf32.f32 "
        "{%0,%1,%2,%3}, {%4,%5,%6,%7}, {%8,%9}, {%0,%1,%2,%3};"
        : "+f"(d[0]), "+f"(d[1]), "+f"(d[2]), "+f"(d[3])
        : "r"(a[0]), "r"(a[1]), "r"(a[2]), "r"(a[3]), "r"(b[0]), "r"(b[1]));
}

// ---------------------------------------------------------------------------
// Kernel 1: transpose x (B,C,H,W) -> (B, DG, H, W, Cg)
// ---------------------------------------------------------------------------
__global__ void transpose_x_kernel(const float* __restrict__ x) {
    int blk = blockIdx.x;
    int y   = blk & (HN - 1);
    int bdg = blk >> 7;
    int b   = bdg >> 3;
    int dg  = bdg & 7;
    int t   = threadIdx.x;

    __shared__ float sm[CG][WN + 1];
    #pragma unroll
    for (int c = 0; c < CG; c++)
        sm[c][t] = x[((b * CN + dg * CG + c) * HN + y) * WN + t];
    __syncthreads();

    float* outp = g_xt + ((bdg * HN + y) * WN + t) * CG;
    #pragma unroll
    for (int i = 0; i < 4; i++) {
        float4 v = make_float4(sm[i * 4 + 0][t], sm[i * 4 + 1][t],
                               sm[i * 4 + 2][t], sm[i * 4 + 3][t]);
        *(float4*)(outp + i * 4) = v;
    }
}

// ---------------------------------------------------------------------------
// Kernel 2: weight -> A-fragment-ordered tf32 (same layout as R5; verified)
// ---------------------------------------------------------------------------
__global__ void prep_w_kernel(const float* __restrict__ w) {
    int i = blockIdx.x * 256 + threadIdx.x;
    if (i >= KT * 8 * 32 * 4) return;
    int j    = i & 3;
    int lane = (i >> 2) & 31;
    int mt   = (i >> 7) & 7;
    int kt   = i >> 10;
    int g    = lane >> 2;
    int tid  = lane & 3;
    int co   = mt * 16 + g + ((j & 1) ? 8 : 0);
    int col  = tid + ((j >= 2) ? 4 : 0);
    int s    = kt >> 1;
    int c    = (kt & 1) * 8 + col;
    int dg   = s / KK;
    int k    = s - dg * KK;
    g_wa[i] = f2tf32(w[(co * CN + dg * CG + c) * KK + k]);
}

// ---------------------------------------------------------------------------
// Corner prefetch state: 4 corner float4s (4 channels) + folded weights
// ---------------------------------------------------------------------------
struct Corners { float4 c[4]; float w[4]; };

__device__ __forceinline__ void issue_corners(int s, int b, int ho, int wo, int q,
                                              float dy, float dx, float m,
                                              Corners& C) {
    int dg = s / KK, k = s - dg * KK;
    int ky = k / 3, kx = k - ky * 3;
    float sy = dy + (float)(ho - 1 + ky);   // STRIDE=1, PAD=1, DIL=1
    float sx = dx + (float)(wo - 1 + kx);
    float y0f = floorf(sy), x0f = floorf(sx);
    float ly = sy - y0f, lx = sx - x0f;
    int y0 = (int)y0f, x0 = (int)x0f;
    float ww[4] = {(1.0f - ly) * (1.0f - lx) * m, (1.0f - ly) * lx * m,
                   ly * (1.0f - lx) * m,          ly * lx * m};
    const float* xb = g_xt + (b * DGN + dg) * (HN * WN * CG) + q * 4;
    #pragma unroll
    for (int i = 0; i < 4; i++) {
        int yy = y0 + (i >> 1), xx = x0 + (i & 1);
        bool v = (yy >= 0) & (yy < HN) & (xx >= 0) & (xx < WN);
        int cy = min(max(yy, 0), HN - 1), cx = min(max(xx, 0), WN - 1);
        C.c[i] = __ldg((const float4*)(xb + (cy * WN + cx) * CG));
        C.w[i] = v ? ww[i] : 0.0f;
    }
}

// ---------------------------------------------------------------------------
// Kernel 3: pipelined deformable sampling + tf32 mma.sync implicit GEMM.
// 512 threads / 16 warps per (b,ho) block. Warp tile 32(co) x 32(px).
// Double-buffered A/B fragment tiles; corners prefetched one stage ahead;
// A tiles staged with cp.async; offsets prefetched two stages ahead.
// ---------------------------------------------------------------------------
__global__ __launch_bounds__(512)
void dcn_main_kernel(const float* __restrict__ offset,
                     const float* __restrict__ mask,
                     const float* __restrict__ bias,
                     float*       __restrict__ out) {
    int blk = blockIdx.x;
    int ho  = blk & (HO - 1);
    int b   = blk >> 7;
    int t   = threadIdx.x;
    int wid = t >> 5;
    int lane = t & 31;

    // B frags: [buf][kt][ntile][lane*2+half] u32  -> 16KB
    __shared__ __align__(16) uint32_t bfr[2][2][16][64];
    // A frags: [buf][kt][mtile][lane] uint4       -> 16KB
    __shared__ __align__(16) uint4 afr[2][2][8][32];

    int m0 = (wid & 3) * 2;    // 2 mtiles per warp
    int n0 = (wid >> 2) * 4;   // 4 ntiles per warp

    // sampling role: pixel wo, channel quarter q (4 channels)
    int wo    = t & (WO - 1);
    int q     = t >> 7;        // 0..3
    int kt    = q >> 1;        // k8-slice within stage
    int rhalf = q & 1;         // rows 0-3 (b0) vs 4-7 (b1)

    float d[2][4][4];
    #pragma unroll
    for (int mi = 0; mi < 2; mi++)
        #pragma unroll
        for (int ni = 0; ni < 4; ni++)
            #pragma unroll
            for (int j = 0; j < 4; j++) d[mi][ni][j] = 0.0f;

    // ---- prologue: offs(0) -> corners(0) issued; offs(1) loaded ----
    Corners C;
    float dyN, dxN, mN;
    {
        int oidx = ((b * (2 * NS)) * HO + ho) * WO + wo;
        float dy0 = __ldg(offset + oidx);
        float dx0 = __ldg(offset + oidx + HO * WO);
        float m0v = __ldg(mask + (b * NS * HO + ho) * WO + wo);
        issue_corners(0, b, ho, wo, q, dy0, dx0, m0v, C);
        int oidx1 = ((b * (2 * NS) + 2) * HO + ho) * WO + wo;
        dyN = __ldg(offset + oidx1);
        dxN = __ldg(offset + oidx1 + HO * WO);
        mN  = __ldg(mask + ((b * NS + 1) * HO + ho) * WO + wo);
    }

    for (int s = 0; s < NS; s++) {
        int buf = s & 1;
        __syncthreads();   // buffers (buf) free: MMA(s-2) done

        // ---- stage A(s) via cp.async (one 16B chunk per thread) ----
        {
            uint32_t dst = s2u(&afr[buf][0][0][0]) + (uint32_t)(t * 16);
            const void* src = (const void*)(g_wa + s * 2048 + t * 4);
            asm volatile("cp.async.cg.shared.global [%0], [%1], 16;"
                         :: "r"(dst), "l"(src) : "memory");
            asm volatile("cp.async.commit_group;" ::: "memory");
        }

        // ---- consume corners(s): bilinear combine + write B frags ----
        {
            float val[4];
            #pragma unroll
            for (int j = 0; j < 4; j++) {
                float* f0 = (float*)&C.c[0];
                float* f1 = (float*)&C.c[1];
                float* f2 = (float*)&C.c[2];
                float* f3 = (float*)&C.c[3];
                val[j] = C.w[0] * f0[j] + C.w[1] * f1[j]
                       + C.w[2] * f2[j] + C.w[3] * f3[j];
            }
            int nt = wo >> 3;
            int lbase = (wo & 7) * 4;
            #pragma unroll
            for (int r = 0; r < 4; r++)
                bfr[buf][kt][nt][(lbase + r) * 2 + rhalf] = f2tf32(val[r]);
        }

        // ---- issue corners(s+1); refill offs(s+2) ----
        if (s + 1 < NS) {
            issue_corners(s + 1, b, ho, wo, q, dyN, dxN, mN, C);
            if (s + 2 < NS) {
                int oidx = ((b * (2 * NS) + 2 * (s + 2)) * HO + ho) * WO + wo;
                dyN = __ldg(offset + oidx);
                dxN = __ldg(offset + oidx + HO * WO);
                mN  = __ldg(mask + ((b * NS + s + 2) * HO + ho) * WO + wo);
            }
        }

        asm volatile("cp.async.wait_group 0;" ::: "memory");
        __syncthreads();   // frags(s) ready

        // ---- GEMM(s): 2 k8-slices x 2 mtiles x 4 ntiles ----
        #pragma unroll
        for (int k2 = 0; k2 < 2; k2++) {
            uint4 af[2];
            #pragma unroll
            for (int mi = 0; mi < 2; mi++) af[mi] = afr[buf][k2][m0 + mi][lane];
            uint2 bf[4];
            #pragma unroll
            for (int ni = 0; ni < 4; ni++)
                bf[ni] = *(const uint2*)&bfr[buf][k2][n0 + ni][lane * 2];
            #pragma unroll
            for (int mi = 0; mi < 2; mi++)
                #pragma unroll
                for (int ni = 0; ni < 4; ni++)
                    mma_tf32(d[mi][ni], (const uint32_t*)&af[mi],
                             (const uint32_t*)&bf[ni]);
        }
    }

    // ---- epilogue ----
    int g   = lane >> 2;
    int tid = lane & 3;
    #pragma unroll
    for (int mi = 0; mi < 2; mi++) {
        int co0 = (m0 + mi) * 16 + g;
        float bv0 = __ldg(bias + co0);
        float bv1 = __ldg(bias + co0 + 8);
        #pragma unroll
        for (int ni = 0; ni < 4; ni++) {
            int px = (n0 + ni) * 8 + 2 * tid;
            float2 o0 = make_float2(d[mi][ni][0] + bv0, d[mi][ni][1] + bv0);
            float2 o1 = make_float2(d[mi][ni][2] + bv1, d[mi][ni][3] + bv1);
            *(float2*)(out + ((b * COUT + co0)     * HO + ho) * WO + px) = o0;
            *(float2*)(out + ((b * COUT + co0 + 8) * HO + ho) * WO + px) = o1;
        }
    }
}

// ---------------------------------------------------------------------------
// Launch
// ---------------------------------------------------------------------------
extern "C" void kernel_launch(void* const* d_in, const int* in_sizes, int n_in,
                              void* d_out, int out_size) {
    const float* x      = (const float*)d_in[0];
    const float* offset = (const float*)d_in[1];
    const float* mask   = (const float*)d_in[2];
    const float* weight = (const float*)d_in[3];
    const float* bias   = (const float*)d_in[4];
    float* out = (float*)d_out;

    transpose_x_kernel<<<BN * DGN * HN, 128>>>(x);
    prep_w_kernel<<<(KT * 8 * 32 * 4 + 255) / 256, 256>>>(weight);
    dcn_main_kernel<<<BN * HO, 512>>>(offset, mask, bias, out);
}

// round 7
// speedup vs baseline: 1.2374x; 1.2374x over previous
#include <cuda_runtime.h>
#include <cstdint>

// Problem constants
#define BN   4
#define CN   128
#define HN   128
#define WN   128
#define COUT 128
#define DGN  8
#define CG   16
#define KK   9
#define HO   128
#define WO   128
#define NS   72         // (dg,k) positions
#define KT   (NS * 2)   // k8 slices (K = 1152)

// Scratch
__device__ __align__(16) float g_xt[BN * DGN * HN * WN * CG];    // x -> (B,DG,H,W,Cg)
__device__ __align__(16) uint32_t g_wa[KT * 8 * 32 * 4];         // A-fragment-ordered tf32 weights

__device__ __forceinline__ uint32_t f2tf32(float v) {
    uint32_t r;
    asm("cvt.rna.tf32.f32 %0, %1;" : "=r"(r) : "f"(v));
    return r;
}
__device__ __forceinline__ void mma_tf32(float* d, const uint32_t* a, const uint32_t* b) {
    asm volatile(
        "mma.sync.aligned.m16n8k8.row.col.f32.tf32.tf32.f32 "
        "{%0,%1,%2,%3}, {%4,%5,%6,%7}, {%8,%9}, {%0,%1,%2,%3};"
        : "+f"(d[0]), "+f"(d[1]), "+f"(d[2]), "+f"(d[3])
        : "r"(a[0]), "r"(a[1]), "r"(a[2]), "r"(a[3]), "r"(b[0]), "r"(b[1]));
}

// ---------------------------------------------------------------------------
// Kernel 1: transpose x (B,C,H,W) -> (B, DG, H, W, Cg)
// ---------------------------------------------------------------------------
__global__ void transpose_x_kernel(const float* __restrict__ x) {
    int blk = blockIdx.x;
    int y   = blk & (HN - 1);
    int bdg = blk >> 7;
    int b   = bdg >> 3;
    int dg  = bdg & 7;
    int t   = threadIdx.x;

    __shared__ float sm[CG][WN + 1];
    #pragma unroll
    for (int c = 0; c < CG; c++)
        sm[c][t] = x[((b * CN + dg * CG + c) * HN + y) * WN + t];
    __syncthreads();

    float* outp = g_xt + ((bdg * HN + y) * WN + t) * CG;
    #pragma unroll
    for (int i = 0; i < 4; i++) {
        float4 v = make_float4(sm[i * 4 + 0][t], sm[i * 4 + 1][t],
                               sm[i * 4 + 2][t], sm[i * 4 + 3][t]);
        *(float4*)(outp + i * 4) = v;
    }
}

// ---------------------------------------------------------------------------
// Kernel 2: weight -> A-fragment-ordered tf32 (verified layout from R5)
// ---------------------------------------------------------------------------
__global__ void prep_w_kernel(const float* __restrict__ w) {
    int i = blockIdx.x * 256 + threadIdx.x;
    if (i >= KT * 8 * 32 * 4) return;
    int j    = i & 3;
    int lane = (i >> 2) & 31;
    int mt   = (i >> 7) & 7;
    int kt   = i >> 10;
    int g    = lane >> 2;
    int tid  = lane & 3;
    int co   = mt * 16 + g + ((j & 1) ? 8 : 0);
    int col  = tid + ((j >= 2) ? 4 : 0);
    int s    = kt >> 1;
    int c    = (kt & 1) * 8 + col;
    int dg   = s / KK;
    int k    = s - dg * KK;
    g_wa[i] = f2tf32(w[(co * CN + dg * CG + c) * KK + k]);
}

// ---------------------------------------------------------------------------
// Corner prefetch state: 8 channels (2 float4 per corner) + folded weights
// ---------------------------------------------------------------------------
struct Corners8 { float4 c[4][2]; float w[4]; };

__device__ __forceinline__ void issue_corners8(int s, int b, int ho, int wo, int ch,
                                               float dy, float dx, float m,
                                               Corners8& C) {
    int dg = s / KK, k = s - dg * KK;
    int ky = k / 3, kx = k - ky * 3;
    float sy = dy + (float)(ho - 1 + ky);   // STRIDE=1, PAD=1, DIL=1
    float sx = dx + (float)(wo - 1 + kx);
    float y0f = floorf(sy), x0f = floorf(sx);
    float ly = sy - y0f, lx = sx - x0f;
    int y0 = (int)y0f, x0 = (int)x0f;
    float ww[4] = {(1.0f - ly) * (1.0f - lx) * m, (1.0f - ly) * lx * m,
                   ly * (1.0f - lx) * m,          ly * lx * m};
    const float* xb = g_xt + (b * DGN + dg) * (HN * WN * CG) + ch;
    #pragma unroll
    for (int i = 0; i < 4; i++) {
        int yy = y0 + (i >> 1), xx = x0 + (i & 1);
        bool v = (yy >= 0) & (yy < HN) & (xx >= 0) & (xx < WN);
        int cy = min(max(yy, 0), HN - 1), cx = min(max(xx, 0), WN - 1);
        const float4* p = (const float4*)(xb + (cy * WN + cx) * CG);
        C.c[i][0] = __ldg(p);
        C.c[i][1] = __ldg(p + 1);
        C.w[i] = v ? ww[i] : 0.0f;
    }
}

// ---------------------------------------------------------------------------
// Kernel 3: single-sync pipelined sampling + tf32 mma.sync implicit GEMM.
// R5 skeleton: 256 threads / 8 warps, warp tile 64(co) x 32(px), 32 MMA/stage.
// Double-buffered frag tiles, ONE __syncthreads per stage, corner + A-slice
// register prefetch one stage ahead, offsets two ahead.
// ---------------------------------------------------------------------------
__global__ __launch_bounds__(256)
void dcn_main_kernel(const float* __restrict__ offset,
                     const float* __restrict__ mask,
                     const float* __restrict__ bias,
                     float*       __restrict__ out) {
    int blk = blockIdx.x;
    int ho  = blk & (HO - 1);
    int b   = blk >> 7;
    int t   = threadIdx.x;
    int wid = t >> 5;
    int lane = t & 31;

    // B frags: [buf][kt][ntile][lane] uint2 -> 16KB
    __shared__ __align__(16) uint2 bfrag[2][2][16][32];
    // A frags: [buf][kt][mtile][lane] uint4 -> 16KB
    __shared__ __align__(16) uint4 afrag[2][2][8][32];

    int m0 = (wid >> 2) * 4;
    int n0 = (wid & 3) * 4;

    // sampling role
    int wo    = t & (WO - 1);
    int ktile = t >> 7;          // 0 or 1
    int ch    = ktile * 8;

    float d[4][4][4];
    #pragma unroll
    for (int mi = 0; mi < 4; mi++)
        #pragma unroll
        for (int ni = 0; ni < 4; ni++)
            #pragma unroll
            for (int j = 0; j < 4; j++) d[mi][ni][j] = 0.0f;

    // ---- prologue ----
    Corners8 C;
    uint4 aP0, aP1;            // A-slice prefetch registers
    float dyN, dxN, mN;        // offsets for stage s+1
    {
        int oidx = ((b * (2 * NS)) * HO + ho) * WO + wo;
        float dy0 = __ldg(offset + oidx);
        float dx0 = __ldg(offset + oidx + HO * WO);
        float m0v = __ldg(mask + (b * NS * HO + ho) * WO + wo);
        issue_corners8(0, b, ho, wo, ch, dy0, dx0, m0v, C);

        int oidx1 = ((b * (2 * NS) + 2) * HO + ho) * WO + wo;
        dyN = __ldg(offset + oidx1);
        dxN = __ldg(offset + oidx1 + HO * WO);
        mN  = __ldg(mask + ((b * NS + 1) * HO + ho) * WO + wo);

        const uint4* wsrc = (const uint4*)g_wa;   // stage 0 slice
        aP0 = __ldg(wsrc + t);
        aP1 = __ldg(wsrc + t + 256);
    }

    for (int s = 0; s < NS; s++) {
        int buf = s & 1;

        // ---- store prefetched A(s) into afrag[buf] ----
        {
            uint4* wdst = (uint4*)&afrag[buf][0][0][0];
            wdst[t]       = aP0;
            wdst[t + 256] = aP1;
        }

        // ---- combine prefetched corners(s) -> B frags ----
        {
            float val[8];
            #pragma unroll
            for (int j = 0; j < 8; j++) val[j] = 0.0f;
            #pragma unroll
            for (int i = 0; i < 4; i++) {
                float wg = C.w[i];
                const float* f0 = (const float*)&C.c[i][0];
                const float* f1 = (const float*)&C.c[i][1];
                val[0] += wg * f0[0];  val[1] += wg * f0[1];
                val[2] += wg * f0[2];  val[3] += wg * f0[3];
                val[4] += wg * f1[0];  val[5] += wg * f1[1];
                val[6] += wg * f1[2];  val[7] += wg * f1[3];
            }
            #pragma unroll
            for (int r = 0; r < 4; r++) {
                uint2 u = make_uint2(f2tf32(val[r]), f2tf32(val[r + 4]));
                bfrag[buf][ktile][wo >> 3][(wo & 7) * 4 + r] = u;
            }
        }

        // ---- issue prefetches for stage s+1 (hide under sync + GEMM) ----
        if (s + 1 < NS) {
            issue_corners8(s + 1, b, ho, wo, ch, dyN, dxN, mN, C);
            const uint4* wsrc = (const uint4*)(g_wa + (s + 1) * 2048);
            aP0 = __ldg(wsrc + t);
            aP1 = __ldg(wsrc + t + 256);
            if (s + 2 < NS) {
                int oidx = ((b * (2 * NS) + 2 * (s + 2)) * HO + ho) * WO + wo;
                dyN = __ldg(offset + oidx);
                dxN = __ldg(offset + oidx + HO * WO);
                mN  = __ldg(mask + ((b * NS + s + 2) * HO + ho) * WO + wo);
            }
        }

        __syncthreads();   // frags(s) visible; buf^1 free for next iteration

        // ---- GEMM(s): 2 k8-slices x 4 mtiles x 4 ntiles m16n8k8 ----
        #pragma unroll
        for (int k2 = 0; k2 < 2; k2++) {
            uint4 af[4];
            #pragma unroll
            for (int mi = 0; mi < 4; mi++) af[mi] = afrag[buf][k2][m0 + mi][lane];
            uint2 bf[4];
            #pragma unroll
            for (int ni = 0; ni < 4; ni++) bf[ni] = bfrag[buf][k2][n0 + ni][lane];
            #pragma unroll
            for (int mi = 0; mi < 4; mi++)
                #pragma unroll
                for (int ni = 0; ni < 4; ni++)
                    mma_tf32(d[mi][ni], (const uint32_t*)&af[mi],
                             (const uint32_t*)&bf[ni]);
        }
    }

    // ---- epilogue ----
    int g   = lane >> 2;
    int tid = lane & 3;
    #pragma unroll
    for (int mi = 0; mi < 4; mi++) {
        int co0 = (m0 + mi) * 16 + g;
        float bv0 = __ldg(bias + co0);
        float bv1 = __ldg(bias + co0 + 8);
        #pragma unroll
        for (int ni = 0; ni < 4; ni++) {
            int px = (n0 + ni) * 8 + 2 * tid;
            float2 o0 = make_float2(d[mi][ni][0] + bv0, d[mi][ni][1] + bv0);
            float2 o1 = make_float2(d[mi][ni][2] + bv1, d[mi][ni][3] + bv1);
            *(float2*)(out + ((b * COUT + co0)     * HO + ho) * WO + px) = o0;
            *(float2*)(out + ((b * COUT + co0 + 8) * HO + ho) * WO + px) = o1;
        }
    }
}

// ---------------------------------------------------------------------------
// Launch
// ---------------------------------------------------------------------------
extern "C" void kernel_launch(void* const* d_in, const int* in_sizes, int n_in,
                              void* d_out, int out_size) {
    const float* x      = (const float*)d_in[0];
    const float* offset = (const float*)d_in[1];
    const float* mask   = (const float*)d_in[2];
    const float* weight = (const float*)d_in[3];
    const float* bias   = (const float*)d_in[4];
    float* out = (float*)d_out;

    transpose_x_kernel<<<BN * DGN * HN, 128>>>(x);
    prep_w_kernel<<<(KT * 8 * 32 * 4 + 255) / 256, 256>>>(weight);
    dcn_main_kernel<<<BN * HO, 256>>>(offset, mask, bias, out);
}

// round 8
// speedup vs baseline: 1.5884x; 1.2836x over previous
#include <cuda_runtime.h>
#include <cstdint>

// Problem constants
#define BN   4
#define CN   128
#define HN   128
#define WN   128
#define COUT 128
#define DGN  8
#define CG   16
#define KK   9
#define HO   128
#define WO   128
#define NS   72         // (dg,k) positions
#define KT   (NS * 2)   // k8 slices (K = 1152)

// Scratch
__device__ __align__(16) float g_xt[BN * DGN * HN * WN * CG];    // x -> (B,DG,H,W,Cg)
__device__ __align__(16) uint32_t g_wa[KT * 8 * 32 * 4];         // A-fragment-ordered tf32 weights

__device__ __forceinline__ uint32_t f2tf32(float v) {
    uint32_t r;
    asm("cvt.rna.tf32.f32 %0, %1;" : "=r"(r) : "f"(v));
    return r;
}
__device__ __forceinline__ void mma_tf32(float* d, const uint32_t* a, const uint32_t* b) {
    asm volatile(
        "mma.sync.aligned.m16n8k8.row.col.f32.tf32.tf32.f32 "
        "{%0,%1,%2,%3}, {%4,%5,%6,%7}, {%8,%9}, {%0,%1,%2,%3};"
        : "+f"(d[0]), "+f"(d[1]), "+f"(d[2]), "+f"(d[3])
        : "r"(a[0]), "r"(a[1]), "r"(a[2]), "r"(a[3]), "r"(b[0]), "r"(b[1]));
}

// ---------------------------------------------------------------------------
// Kernel 1: transpose x (B,C,H,W) -> (B, DG, H, W, Cg)
// ---------------------------------------------------------------------------
__global__ void transpose_x_kernel(const float* __restrict__ x) {
    int blk = blockIdx.x;
    int y   = blk & (HN - 1);
    int bdg = blk >> 7;
    int b   = bdg >> 3;
    int dg  = bdg & 7;
    int t   = threadIdx.x;

    __shared__ float sm[CG][WN + 1];
    #pragma unroll
    for (int c = 0; c < CG; c++)
        sm[c][t] = x[((b * CN + dg * CG + c) * HN + y) * WN + t];
    __syncthreads();

    float* outp = g_xt + ((bdg * HN + y) * WN + t) * CG;
    #pragma unroll
    for (int i = 0; i < 4; i++) {
        float4 v = make_float4(sm[i * 4 + 0][t], sm[i * 4 + 1][t],
                               sm[i * 4 + 2][t], sm[i * 4 + 3][t]);
        *(float4*)(outp + i * 4) = v;
    }
}

// ---------------------------------------------------------------------------
// Kernel 2: weight -> A-fragment-ordered tf32 (verified layout)
// ---------------------------------------------------------------------------
__global__ void prep_w_kernel(const float* __restrict__ w) {
    int i = blockIdx.x * 256 + threadIdx.x;
    if (i >= KT * 8 * 32 * 4) return;
    int j    = i & 3;
    int lane = (i >> 2) & 31;
    int mt   = (i >> 7) & 7;
    int kt   = i >> 10;
    int g    = lane >> 2;
    int tid  = lane & 3;
    int co   = mt * 16 + g + ((j & 1) ? 8 : 0);
    int col  = tid + ((j >= 2) ? 4 : 0);
    int s    = kt >> 1;
    int c    = (kt & 1) * 8 + col;
    int dg   = s / KK;
    int k    = s - dg * KK;
    g_wa[i] = f2tf32(w[(co * CN + dg * CG + c) * KK + k]);
}

// ---------------------------------------------------------------------------
// Corner prefetch state: 4 channels (one float4 per corner) + folded weights
// ---------------------------------------------------------------------------
struct C4 { float4 c[4]; float w[4]; };

__device__ __forceinline__ void issue_c4(int s, int b, int ho, int p, int q,
                                         float dy, float dx, float m, C4& C) {
    int dg = s / KK, k = s - dg * KK;
    int ky = k / 3, kx = k - ky * 3;
    float sy = dy + (float)(ho - 1 + ky);   // STRIDE=1, PAD=1, DIL=1
    float sx = dx + (float)(p - 1 + kx);
    float y0f = floorf(sy), x0f = floorf(sx);
    float ly = sy - y0f, lx = sx - x0f;
    int y0 = (int)y0f, x0 = (int)x0f;
    float ww[4] = {(1.0f - ly) * (1.0f - lx) * m, (1.0f - ly) * lx * m,
                   ly * (1.0f - lx) * m,          ly * lx * m};
    const float* xb = g_xt + (b * DGN + dg) * (HN * WN * CG) + q * 4;
    #pragma unroll
    for (int i = 0; i < 4; i++) {
        int yy = y0 + (i >> 1), xx = x0 + (i & 1);
        bool v = (yy >= 0) & (yy < HN) & (xx >= 0) & (xx < WN);
        int cy = min(max(yy, 0), HN - 1), cx = min(max(xx, 0), WN - 1);
        C.c[i] = __ldg((const float4*)(xb + (cy * WN + cx) * CG));
        C.w[i] = v ? ww[i] : 0.0f;
    }
}

// ---------------------------------------------------------------------------
// Kernel 3: coalesced-gather pipelined sampling + tf32 mma.sync GEMM.
// 256 threads / 8 warps, warp tile 64(co) x 32(px), single sync per stage.
// Sampler mapping: lane = pixel*4 + quarter  -> each corner LDG.128 has
// 4-lane groups contiguous in one 128B line (~8-12 lines/instr vs 32).
// Two pixel passes per stage (p and p+64), 4 channels per thread per pass.
// ---------------------------------------------------------------------------
__global__ __launch_bounds__(256)
void dcn_main_kernel(const float* __restrict__ offset,
                     const float* __restrict__ mask,
                     const float* __restrict__ bias,
                     float*       __restrict__ out) {
    int blk = blockIdx.x;
    int ho  = blk & (HO - 1);
    int b   = blk >> 7;
    int t   = threadIdx.x;
    int wid = t >> 5;
    int lane = t & 31;

    // B frags: [buf][kt][ntile][lane][half] u32 -> 16KB
    __shared__ __align__(16) uint32_t bfr[2][2][16][32][2];
    // A frags: [buf][kt][mtile][lane] uint4     -> 16KB
    __shared__ __align__(16) uint4 afrag[2][2][8][32];

    int m0 = (wid >> 2) * 4;
    int n0 = (wid & 3) * 4;

    // sampler mapping: 4 threads per pixel, two pixel passes
    int q    = t & 3;          // channel quarter: channels q*4 .. q*4+3
    int p0   = t >> 2;         // pass-0 pixel (0..63)
    int p1   = p0 + 64;        // pass-1 pixel
    int kt   = q >> 1;         // k8-slice
    int half = q & 1;          // b0 (rows 0-3) vs b1 (rows 4-7)

    float d[4][4][4];
    #pragma unroll
    for (int mi = 0; mi < 4; mi++)
        #pragma unroll
        for (int ni = 0; ni < 4; ni++)
            #pragma unroll
            for (int j = 0; j < 4; j++) d[mi][ni][j] = 0.0f;

    // ---- prologue ----
    C4 CA, CB;
    uint4 aP0, aP1;
    float dyA, dxA, mA, dyB, dxB, mB;   // offsets for the NEXT stage to issue
    {
        int ob = ((b * (2 * NS)) * HO + ho) * WO;
        int mb0 = (b * NS * HO + ho) * WO;
        float dy0A = __ldg(offset + ob + p0);
        float dx0A = __ldg(offset + ob + HO * WO + p0);
        float m0A  = __ldg(mask + mb0 + p0);
        float dy0B = __ldg(offset + ob + p1);
        float dx0B = __ldg(offset + ob + HO * WO + p1);
        float m0B  = __ldg(mask + mb0 + p1);
        issue_c4(0, b, ho, p0, q, dy0A, dx0A, m0A, CA);
        issue_c4(0, b, ho, p1, q, dy0B, dx0B, m0B, CB);

        int ob1 = ((b * (2 * NS) + 2) * HO + ho) * WO;
        int mb1 = ((b * NS + 1) * HO + ho) * WO;
        dyA = __ldg(offset + ob1 + p0);
        dxA = __ldg(offset + ob1 + HO * WO + p0);
        mA  = __ldg(mask + mb1 + p0);
        dyB = __ldg(offset + ob1 + p1);
        dxB = __ldg(offset + ob1 + HO * WO + p1);
        mB  = __ldg(mask + mb1 + p1);

        const uint4* wsrc = (const uint4*)g_wa;
        aP0 = __ldg(wsrc + t);
        aP1 = __ldg(wsrc + t + 256);
    }

    for (int s = 0; s < NS; s++) {
        int buf = s & 1;

        // ---- store prefetched A(s) ----
        {
            uint4* wdst = (uint4*)&afrag[buf][0][0][0];
            wdst[t]       = aP0;
            wdst[t + 256] = aP1;
        }

        // ---- combine prefetched corners(s) -> B frags (both passes) ----
        #pragma unroll
        for (int pp = 0; pp < 2; pp++) {
            const C4& C = pp ? CB : CA;
            int p = pp ? p1 : p0;
            float val[4];
            #pragma unroll
            for (int c = 0; c < 4; c++) {
                const float* f0 = (const float*)&C.c[0];
                const float* f1 = (const float*)&C.c[1];
                const float* f2 = (const float*)&C.c[2];
                const float* f3 = (const float*)&C.c[3];
                val[c] = C.w[0] * f0[c] + C.w[1] * f1[c]
                       + C.w[2] * f2[c] + C.w[3] * f3[c];
            }
            int nt = p >> 3;
            int lb = (p & 7) * 4;
            #pragma unroll
            for (int c = 0; c < 4; c++)
                bfr[buf][kt][nt][lb + c][half] = f2tf32(val[c]);
        }

        // ---- issue prefetches for stage s+1 ----
        if (s + 1 < NS) {
            issue_c4(s + 1, b, ho, p0, q, dyA, dxA, mA, CA);
            issue_c4(s + 1, b, ho, p1, q, dyB, dxB, mB, CB);
            const uint4* wsrc = (const uint4*)(g_wa + (s + 1) * 2048);
            aP0 = __ldg(wsrc + t);
            aP1 = __ldg(wsrc + t + 256);
            if (s + 2 < NS) {
                int ob = ((b * (2 * NS) + 2 * (s + 2)) * HO + ho) * WO;
                int mbi = ((b * NS + s + 2) * HO + ho) * WO;
                dyA = __ldg(offset + ob + p0);
                dxA = __ldg(offset + ob + HO * WO + p0);
                mA  = __ldg(mask + mbi + p0);
                dyB = __ldg(offset + ob + p1);
                dxB = __ldg(offset + ob + HO * WO + p1);
                mB  = __ldg(mask + mbi + p1);
            }
        }

        __syncthreads();   // frags(s) visible; other buffer free

        // ---- GEMM(s): 2 k8-slices x 4 mtiles x 4 ntiles m16n8k8 ----
        #pragma unroll
        for (int k2 = 0; k2 < 2; k2++) {
            uint4 af[4];
            #pragma unroll
            for (int mi = 0; mi < 4; mi++) af[mi] = afrag[buf][k2][m0 + mi][lane];
            uint2 bf[4];
            #pragma unroll
            for (int ni = 0; ni < 4; ni++)
                bf[ni] = *(const uint2*)&bfr[buf][k2][n0 + ni][lane][0];
            #pragma unroll
            for (int mi = 0; mi < 4; mi++)
                #pragma unroll
                for (int ni = 0; ni < 4; ni++)
                    mma_tf32(d[mi][ni], (const uint32_t*)&af[mi],
                             (const uint32_t*)&bf[ni]);
        }
    }

    // ---- epilogue ----
    int g   = lane >> 2;
    int tid = lane & 3;
    #pragma unroll
    for (int mi = 0; mi < 4; mi++) {
        int co0 = (m0 + mi) * 16 + g;
        float bv0 = __ldg(bias + co0);
        float bv1 = __ldg(bias + co0 + 8);
        #pragma unroll
        for (int ni = 0; ni < 4; ni++) {
            int px = (n0 + ni) * 8 + 2 * tid;
            float2 o0 = make_float2(d[mi][ni][0] + bv0, d[mi][ni][1] + bv0);
            float2 o1 = make_float2(d[mi][ni][2] + bv1, d[mi][ni][3] + bv1);
            *(float2*)(out + ((b * COUT + co0)     * HO + ho) * WO + px) = o0;
            *(float2*)(out + ((b * COUT + co0 + 8) * HO + ho) * WO + px) = o1;
        }
    }
}

// ---------------------------------------------------------------------------
// Launch
// ---------------------------------------------------------------------------
extern "C" void kernel_launch(void* const* d_in, const int* in_sizes, int n_in,
                              void* d_out, int out_size) {
    const float* x      = (const float*)d_in[0];
    const float* offset = (const float*)d_in[1];
    const float* mask   = (const float*)d_in[2];
    const float* weight = (const float*)d_in[3];
    const float* bias   = (const float*)d_in[4];
    float* out = (float*)d_out;

    transpose_x_kernel<<<BN * DGN * HN, 128>>>(x);
    prep_w_kernel<<<(KT * 8 * 32 * 4 + 255) / 256, 256>>>(weight);
    dcn_main_kernel<<<BN * HO, 256>>>(offset, mask, bias, out);
}